// round 2
// baseline (speedup 1.0000x reference)
#include <cuda_runtime.h>
#include <cuda_bf16.h>
#include <cstdint>

// ---------------------------------------------------------------------------
// Stacked LSTM grid: 64 layers x 64 timesteps, B=128, H=64.
// Persistent pipelined kernel: one CTA per (layer, half-batch).
//   CTA(l, q) : batch rows [q*64, q*64+64)
//   cell(l,t) consumes h from cell(l-1,t) via global buffer + release/acquire flag
//   weights held in SMEM (fp32, 128KB), h state transposed in SMEM, c in registers
//   GEMM M=64,N=256,K=128 in packed fp32x2 FFMA
// ---------------------------------------------------------------------------

#define NT 64      // timesteps
#define NL 64      // layers
#define NB 128     // batch
#define NH 64      // hidden
#define NG 256     // 4*H gates
#define MB 64      // batch rows per CTA (half split)
#define THREADS 256

// producer buffers: layers 0..62 produce for layer above. [l][half][t][b*64+h]
__device__ float g_Hbuf[63][2][NT][MB * NH];
__device__ unsigned int g_flags[63][2][NT];
__device__ float g_pred[NB * NT];

// ---------------- fp32x2 helpers ----------------
__device__ __forceinline__ void fma2(unsigned long long& acc, unsigned long long a,
                                     unsigned long long b) {
    asm("fma.rn.f32x2 %0, %1, %2, %0;" : "+l"(acc) : "l"(a), "l"(b));
}
__device__ __forceinline__ unsigned long long bcast2(float v) {
    unsigned long long r;
    asm("mov.b64 %0, {%1, %2};" : "=l"(r) : "f"(v), "f"(v));
    return r;
}
__device__ __forceinline__ float2 unpack2(unsigned long long p) {
    float2 r;
    asm("mov.b64 {%0, %1}, %2;" : "=f"(r.x), "=f"(r.y) : "l"(p));
    return r;
}

// ---------------- activations (MUFU based, fp32-accurate) ----------------
__device__ __forceinline__ float sigmoidf_(float x) {
    float e = __expf(-x);               // MUFU.EX2 path
    return __fdividef(1.0f, 1.0f + e);  // MUFU.RCP path
}
__device__ __forceinline__ float tanhf_(float x) {
    x = fminf(fmaxf(x, -15.0f), 15.0f);
    float e = __expf(2.0f * x);
    return __fdividef(e - 1.0f, e + 1.0f);
}

// SMEM layout (floats):
//   W_s   [128][256]      32768
//   hT    [128][64]        8192   rows 0..63 = h_in^T, rows 64..127 = h_prev^T
//   z_s   [64][256]       16384
//   bias  [256]
//   w0x   [256]
//   x_s   [64]
#define SMEM_FLOATS (32768 + 8192 + 16384 + 256 + 256 + 64)

__global__ void __launch_bounds__(THREADS, 1) lstm_pipeline_kernel(
    const float* __restrict__ x,   // [B, T, 1]
    const float* __restrict__ W0,  // [65, 256]
    const float* __restrict__ b0,  // [256]
    const float* __restrict__ Wl,  // [63, 128, 256]
    const float* __restrict__ bl,  // [63, 256]
    const float* __restrict__ Wd,  // [64, 64, 1]
    const float* __restrict__ bd)  // [64, 1]
{
    extern __shared__ float sm[];
    float* W_s    = sm;                   // 32768
    float* hT     = sm + 32768;           // 8192
    float* z_s    = sm + 32768 + 8192;    // 16384
    float* bias_s = z_s + 16384;          // 256
    float* w0x    = bias_s + 256;         // 256
    float* x_s    = w0x + 256;            // 64

    const int tid  = threadIdx.x;
    const int half = blockIdx.x;  // 0..1
    const int l    = blockIdx.y;  // 0..63

    // ---- load weights into SMEM (once) ----
    if (l == 0) {
        // rows 64..127 of W_s = W0 rows 1..64 (h_prev part). rows 0..63 unused.
        for (int i = tid; i < 64 * 256; i += THREADS) W_s[64 * 256 + i] = W0[256 + i];
        if (tid < 256) { bias_s[tid] = b0[tid]; w0x[tid] = W0[tid]; }
    } else {
        const float4* wsrc = (const float4*)(Wl + (size_t)(l - 1) * 128 * 256);
        float4* wdst = (float4*)W_s;
        for (int i = tid; i < 128 * 256 / 4; i += THREADS) wdst[i] = wsrc[i];
        if (tid < 256) bias_s[tid] = bl[(l - 1) * 256 + tid];
    }
    // h_prev = 0 (rows 64..127 of hT)
    for (int i = tid; i < 4096; i += THREADS) hT[4096 + i] = 0.0f;

    // cell state in registers: thread owns (b = tid/4, hc in [(tid%4)*16, +16))
    float creg[16];
#pragma unroll
    for (int i = 0; i < 16; i++) creg[i] = 0.0f;

    const int gt = tid & 31;  // g-tile (8 cols each), warp lanes span all 32 gt
    const int bt = tid >> 5;  // b-tile (8 rows each), one per warp
    const int myb   = tid >> 2;
    const int hbase = (tid & 3) * 16;

    __syncthreads();

    for (int t = 0; t < NT; ++t) {
        // ---- acquire input ----
        if (l == 0) {
            if (tid < MB) x_s[tid] = x[(size_t)(half * MB + tid) * NT + t];
            __syncthreads();
        } else {
            if (tid == 0) {
                const unsigned int* fp = &g_flags[l - 1][half][t];
                unsigned int v;
                do {
                    asm volatile("ld.acquire.gpu.global.b32 %0, [%1];"
                                 : "=r"(v) : "l"(fp));
                } while (v == 0u);
            }
            __syncthreads();
            const float* src = &g_Hbuf[l - 1][half][t][0];
            for (int i = tid; i < MB * NH; i += THREADS) {
                int b = i >> 6, k = i & 63;
                hT[k * 64 + b] = src[i];  // transpose into K-major
            }
            __syncthreads();
        }

        // ---- GEMM: z[64,256] = [h_in | h_prev] @ W  (fp32x2) ----
        unsigned long long acc[32];
#pragma unroll
        for (int i = 0; i < 32; i++) acc[i] = 0ull;

        const int kStart = (l == 0) ? 64 : 0;
        const float* aBase = hT + bt * 8;
        const float* wBase = W_s + gt * 8;
#pragma unroll 2
        for (int k = kStart; k < 128; ++k) {
            const float* ar = aBase + k * 64;
            float4 a0 = *(const float4*)ar;
            float4 a1 = *(const float4*)(ar + 4);
            const float* wr = wBase + k * 256;
            ulonglong2 wv0 = *(const ulonglong2*)wr;
            ulonglong2 wv1 = *(const ulonglong2*)(wr + 4);
            unsigned long long wp0 = wv0.x, wp1 = wv0.y, wp2 = wv1.x, wp3 = wv1.y;
            float av[8] = {a0.x, a0.y, a0.z, a0.w, a1.x, a1.y, a1.z, a1.w};
#pragma unroll
            for (int r = 0; r < 8; r++) {
                unsigned long long pa = bcast2(av[r]);
                fma2(acc[r * 4 + 0], pa, wp0);
                fma2(acc[r * 4 + 1], pa, wp1);
                fma2(acc[r * 4 + 2], pa, wp2);
                fma2(acc[r * 4 + 3], pa, wp3);
            }
        }

        // ---- store z (+bias, + x*W0row0 for layer 0) ----
#pragma unroll
        for (int r = 0; r < 8; r++) {
            int b = bt * 8 + r;
            float* zr = z_s + b * 256 + gt * 8;
            float xv = (l == 0) ? x_s[b] : 0.0f;
#pragma unroll
            for (int cp = 0; cp < 4; cp++) {
                float2 v = unpack2(acc[r * 4 + cp]);
                int g = gt * 8 + cp * 2;
                v.x += bias_s[g];
                v.y += bias_s[g + 1];
                if (l == 0) { v.x += xv * w0x[g]; v.y += xv * w0x[g + 1]; }
                zr[cp * 2]     = v.x;
                zr[cp * 2 + 1] = v.y;
            }
        }
        __syncthreads();

        // ---- elementwise LSTM cell ----
        const float* zb = z_s + myb * 256;
        float hout[16];
#pragma unroll
        for (int i = 0; i < 16; i++) {
            int hc = hbase + i;
            float zi = zb[hc];
            float zj = zb[64 + hc];
            float zf = zb[128 + hc];
            float zo = zb[192 + hc];
            float c2 = creg[i] * sigmoidf_(zf) + sigmoidf_(zi) * tanhf_(zj);
            float h2 = tanhf_(c2) * sigmoidf_(zo);
            creg[i] = c2;
            hT[(64 + hc) * 64 + myb] = h2;  // h_prev^T for next timestep
            hout[i] = h2;
        }

        if (l < 63) {
            // publish h to layer above
            float* dst = &g_Hbuf[l][half][t][myb * 64 + hbase];
#pragma unroll
            for (int i = 0; i < 16; i += 4)
                *(float4*)(dst + i) =
                    make_float4(hout[i], hout[i + 1], hout[i + 2], hout[i + 3]);
            __threadfence();
            __syncthreads();
            if (tid == 0) {
                unsigned int one = 1u;
                asm volatile("st.release.gpu.global.b32 [%0], %1;" ::
                                 "l"(&g_flags[l][half][t]), "r"(one));
            }
        } else {
            // top layer: dense head -> pred
            __syncthreads();
            if (tid < MB) {
                int b = tid;
                float s = bd[t];
                const float* wd = Wd + t * 64;
#pragma unroll 8
                for (int h = 0; h < NH; ++h) s += hT[(64 + h) * 64 + b] * wd[h];
                g_pred[(size_t)(half * MB + b) * NT + t] = fmaxf(s, 0.0f);
            }
        }
    }
}

__global__ void reset_flags_kernel() {
    unsigned int i = blockIdx.x * blockDim.x + threadIdx.x;
    if (i < 63u * 2u * NT) ((unsigned int*)g_flags)[i] = 0u;
}

__global__ void finalize_kernel(const float* __restrict__ labels,
                                float* __restrict__ out, int out_size) {
    __shared__ float red[256];
    float s = 0.0f;
    for (int i = threadIdx.x; i < NB * NT; i += 256) {
        float d = labels[i] - g_pred[i];
        s += d * d;
    }
    red[threadIdx.x] = s;
    __syncthreads();
    for (int st = 128; st > 0; st >>= 1) {
        if (threadIdx.x < st) red[threadIdx.x] += red[threadIdx.x + st];
        __syncthreads();
    }
    float loss = red[0] / (float)(NB * NT);

    if (out_size > NB * NT) {
        for (int i = threadIdx.x; i < NB * NT; i += 256) out[i] = g_pred[i];
        if (threadIdx.x == 0)
            for (int i = NB * NT; i < out_size; ++i) out[i] = loss;
    } else if (out_size == NB * NT) {
        for (int i = threadIdx.x; i < NB * NT; i += 256) out[i] = g_pred[i];
    } else {
        for (int i = threadIdx.x; i < out_size; i += 256) out[i] = loss;
    }
}

extern "C" void kernel_launch(void* const* d_in, const int* in_sizes, int n_in,
                              void* d_out, int out_size) {
    const float* x      = (const float*)d_in[0];
    const float* labels = (const float*)d_in[1];
    const float* W0     = (const float*)d_in[2];
    const float* b0     = (const float*)d_in[3];
    const float* Wl     = (const float*)d_in[4];
    const float* bl     = (const float*)d_in[5];
    const float* Wd     = (const float*)d_in[6];
    const float* bd     = (const float*)d_in[7];
    float* out = (float*)d_out;

    size_t smem_bytes = SMEM_FLOATS * sizeof(float);
    cudaFuncSetAttribute(lstm_pipeline_kernel,
                         cudaFuncAttributeMaxDynamicSharedMemorySize,
                         (int)smem_bytes);

    reset_flags_kernel<<<32, 256>>>();
    dim3 grid(2, NL);
    lstm_pipeline_kernel<<<grid, THREADS, smem_bytes>>>(x, W0, b0, Wl, bl, Wd, bd);
    finalize_kernel<<<1, 256>>>(labels, out, out_size);
}

// round 4
// speedup vs baseline: 2.0346x; 2.0346x over previous
#include <cuda_runtime.h>
#include <cuda_bf16.h>
#include <cstdint>

// ---------------------------------------------------------------------------
// 64-layer x 64-timestep stacked LSTM, B=128, H=64.
// 128 persistent CTAs = (layer, batch-half), 256 threads each.
// Per cell: z[64,256] = A[64,128] @ W  via mma.sync.m16n8k16 bf16 (3-term split)
//   A cols 0..63 = h_in (from layer below), 64..127 = h_prev (own)
//   W columns gate-interleaved: n' = h*4 + g  -> fragment-level epilogue with
//   one shfl.xor(1) to assemble all 4 gates per (b,h); c stays in registers.
// ---------------------------------------------------------------------------

#define NT 64
#define NL 64
#define MB 64          // batch rows per CTA
#define THREADS 256
#define LDW 136        // padded SMEM row length (bf16 elems) : 272B, conflict-free ldmatrix

// weights, gate-interleaved + bf16 split: [split][layer][n'*128 + k]
__device__ __nv_bfloat16 g_Wsplit[2][NL][256 * 128];
// h handoff: [l][half][t][b*64+h], packed (hi | lo<<16)
__device__ uint32_t g_Hbuf[63 * 2 * NT * MB * 64];
__device__ unsigned int g_flags[63 * 2 * NT];
__device__ float g_pred[128 * NT];

// ---- SMEM byte offsets ----
#define OFF_WH 0
#define OFF_WL 69632
#define OFF_AH 139264
#define OFF_AL 156672
#define OFF_BIAS 174080
#define OFF_WD 175104
#define OFF_PS 191488
#define SMEM_BYTES 193536

__device__ __forceinline__ uint32_t smem_u32(const void* p) {
    uint32_t a;
    asm("{ .reg .u64 t; cvta.to.shared.u64 t, %1; cvt.u32.u64 %0, t; }"
        : "=r"(a) : "l"(p));
    return a;
}
__device__ __forceinline__ void ldsm4(uint32_t r[4], uint32_t addr) {
    asm volatile("ldmatrix.sync.aligned.m8n8.x4.shared.b16 {%0,%1,%2,%3}, [%4];"
                 : "=r"(r[0]), "=r"(r[1]), "=r"(r[2]), "=r"(r[3]) : "r"(addr));
}
__device__ __forceinline__ void mma_bf16(float d[4], const uint32_t a[4],
                                         uint32_t b0, uint32_t b1) {
    asm volatile(
        "mma.sync.aligned.m16n8k16.row.col.f32.bf16.bf16.f32 "
        "{%0,%1,%2,%3}, {%4,%5,%6,%7}, {%8,%9}, {%0,%1,%2,%3};"
        : "+f"(d[0]), "+f"(d[1]), "+f"(d[2]), "+f"(d[3])
        : "r"(a[0]), "r"(a[1]), "r"(a[2]), "r"(a[3]), "r"(b0), "r"(b1));
}

__device__ __forceinline__ float sigf_(float z) {
    float e = __expf(-z);
    return __fdividef(1.0f, 1.0f + e);
}
__device__ __forceinline__ float tanhf_(float z) {
    z = fminf(fmaxf(z, -15.0f), 15.0f);
    float e = __expf(2.0f * z);
    return __fdividef(e - 1.0f, e + 1.0f);
}

// ---- weight prep: gate-interleave + exact bf16 2-split ----
__global__ void prep_weights(const float* __restrict__ W0,
                             const float* __restrict__ Wl) {
    int i = blockIdx.x * blockDim.x + threadIdx.x;
    if (i >= NL * 32768) return;
    int l = i >> 15, nk = i & 32767;
    int np = nk >> 7, k = nk & 127;          // np = h*4+g
    int h = np >> 2, g = np & 3;
    int n = g * 64 + h;                       // original gate order i,j,f,o
    float w;
    if (l == 0) {
        if (k == 0) w = W0[n];
        else if (k < 64) w = 0.0f;
        else w = W0[(size_t)(k - 63) * 256 + n];
    } else {
        w = Wl[((size_t)(l - 1) * 128 + k) * 256 + n];
    }
    __nv_bfloat16 hi = __float2bfloat16(w);
    __nv_bfloat16 lo = __float2bfloat16(w - __bfloat162float(hi));
    g_Wsplit[0][l][nk] = hi;
    g_Wsplit[1][l][nk] = lo;
}

__global__ void reset_flags_kernel() {
    unsigned int i = blockIdx.x * blockDim.x + threadIdx.x;
    if (i < 63u * 2u * NT) g_flags[i] = 0u;
}

__global__ void __launch_bounds__(THREADS, 1) lstm_mma_kernel(
    const float* __restrict__ x, const float* __restrict__ b0,
    const float* __restrict__ bl, const float* __restrict__ Wd,
    const float* __restrict__ bd) {
    extern __shared__ char sm[];
    const int tid = threadIdx.x, lane = tid & 31, warp = tid >> 5;
    const int half = blockIdx.x, l = blockIdx.y;
    const int mwarp = warp >> 2, nwarp = warp & 3;
    const uint32_t smb = smem_u32(sm);

    float* bias_s = (float*)(sm + OFF_BIAS);
    float* Wd_s   = (float*)(sm + OFF_WD);
    float* ps     = (float*)(sm + OFF_PS);

    // ---- init: weights (both splits), bias, zero A, Wd for top layer ----
    for (int s = 0; s < 2; s++) {
        const uint32_t* src = (const uint32_t*)g_Wsplit[s][l];
        char* dst = sm + (s ? OFF_WL : OFF_WH);
        for (int i = tid; i < 16384; i += THREADS) {
            int n = i >> 6, kk = i & 63;
            *(uint32_t*)(dst + n * (LDW * 2) + kk * 4) = src[i];
        }
    }
    for (int i = tid; i < 256; i += THREADS)
        bias_s[i] = (l == 0) ? b0[i] : bl[(size_t)(l - 1) * 256 + i];
    for (int i = tid; i < (2 * MB * LDW * 2) / 4; i += THREADS)
        ((uint32_t*)(sm + OFF_AH))[i] = 0u;
    if (l == NL - 1)
        for (int i = tid; i < 64 * 64; i += THREADS) Wd_s[i] = Wd[i];
    __syncthreads();

    // per-lane ldmatrix address bases
    const uint32_t aRow = ((uint32_t)((lane & 15) * LDW + (lane >> 4) * 8)) * 2u;
    const uint32_t bRow =
        ((uint32_t)((nwarp * 64 + ((lane >> 4) & 1) * 8 + (lane & 7)) * LDW +
                    ((lane >> 3) & 1) * 8)) * 2u;
    const uint32_t sAH = smb + OFF_AH + aRow;
    const uint32_t sAL = smb + OFF_AL + aRow;
    const uint32_t sWH = smb + OFF_WH + bRow;
    const uint32_t sWL = smb + OFF_WL + bRow;

    const bool evenp = (lane & 1) == 0;
    const int rowb = (lane >> 2) + (evenp ? 0 : 8);
    const int hpar = (lane & 2) >> 1;

    float creg[16];
#pragma unroll
    for (int i = 0; i < 16; i++) creg[i] = 0.0f;

    for (int t = 0; t < NT; ++t) {
        // ---- stage A h_in (or x) ----
        if (l == 0) {
            if (tid < MB) {
                float xv = x[(size_t)(half * MB + tid) * NT + t];
                __nv_bfloat16 hi = __float2bfloat16(xv);
                __nv_bfloat16 lo = __float2bfloat16(xv - __bfloat162float(hi));
                *(unsigned short*)(sm + OFF_AH + tid * (LDW * 2)) =
                    __bfloat16_as_ushort(hi);
                *(unsigned short*)(sm + OFF_AL + tid * (LDW * 2)) =
                    __bfloat16_as_ushort(lo);
            }
        } else {
            if (tid == 0) {
                const unsigned int* fp = &g_flags[((l - 1) * 2 + half) * NT + t];
                unsigned int v;
                do {
                    asm volatile("ld.acquire.gpu.global.b32 %0, [%1];"
                                 : "=r"(v) : "l"(fp));
                } while (v == 0u);
            }
            __syncthreads();
            const uint32_t* src =
                g_Hbuf + (size_t)(((l - 1) * 2 + half) * NT + t) * 4096;
            int b = tid >> 2, h0 = (tid & 3) * 16;
            uint32_t u[16];
            const uint4* s4 = (const uint4*)(src + b * 64 + h0);
#pragma unroll
            for (int j = 0; j < 4; j++) {
                uint4 v = s4[j];
                u[j * 4] = v.x; u[j * 4 + 1] = v.y;
                u[j * 4 + 2] = v.z; u[j * 4 + 3] = v.w;
            }
#pragma unroll
            for (int j = 0; j < 16; j += 2) {
                uint32_t hip = __byte_perm(u[j], u[j + 1], 0x5410);
                uint32_t lop = __byte_perm(u[j], u[j + 1], 0x7632);
                *(uint32_t*)(sm + OFF_AH + b * (LDW * 2) + (h0 + j) * 2) = hip;
                *(uint32_t*)(sm + OFF_AL + b * (LDW * 2) + (h0 + j) * 2) = lop;
            }
        }
        __syncthreads();

        // ---- GEMM: 8 k-chunks x (2 m) x (8 n) x 3 split terms ----
        float acc[2][8][4];
#pragma unroll
        for (int i = 0; i < 2; i++)
#pragma unroll
            for (int j = 0; j < 8; j++)
#pragma unroll
                for (int c = 0; c < 4; c++) acc[i][j][c] = 0.0f;

#pragma unroll 2
        for (int k = 0; k < 8; k++) {
            uint32_t ah[2][4], al[2][4], bh[4][4], bl_[4][4];
            ldsm4(ah[0], sAH + k * 32);
            ldsm4(ah[1], sAH + 16 * LDW * 2 + k * 32);
            ldsm4(al[0], sAL + k * 32);
            ldsm4(al[1], sAL + 16 * LDW * 2 + k * 32);
#pragma unroll
            for (int np = 0; np < 4; np++) {
                ldsm4(bh[np], sWH + np * 16 * LDW * 2 + k * 32);
                ldsm4(bl_[np], sWL + np * 16 * LDW * 2 + k * 32);
            }
#pragma unroll
            for (int mt = 0; mt < 2; mt++)
#pragma unroll
                for (int nt = 0; nt < 8; nt++) {
                    uint32_t h0r = bh[nt >> 1][(nt & 1) * 2];
                    uint32_t h1r = bh[nt >> 1][(nt & 1) * 2 + 1];
                    uint32_t l0r = bl_[nt >> 1][(nt & 1) * 2];
                    uint32_t l1r = bl_[nt >> 1][(nt & 1) * 2 + 1];
                    mma_bf16(acc[mt][nt], ah[mt], h0r, h1r);
                    mma_bf16(acc[mt][nt], ah[mt], l0r, l1r);
                    mma_bf16(acc[mt][nt], al[mt], h0r, h1r);
                }
        }
        __syncthreads();  // all ldmatrix reads of A done before epilogue writes

        // ---- fragment epilogue: exchange gates, LSTM cell ----
        uint32_t* gH = (l < NL - 1)
            ? g_Hbuf + (size_t)((l * 2 + half) * NT + t) * 4096 : (uint32_t*)0;
#pragma unroll
        for (int mt = 0; mt < 2; mt++) {
            float part = 0.0f;
            const int b = mwarp * 32 + mt * 16 + rowb;
#pragma unroll
            for (int nt = 0; nt < 8; nt++) {
                float c0 = acc[mt][nt][0], c1 = acc[mt][nt][1];
                float c2v = acc[mt][nt][2], c3v = acc[mt][nt][3];
                float o0 = __shfl_xor_sync(0xffffffffu, c0, 1);
                float o1 = __shfl_xor_sync(0xffffffffu, c1, 1);
                float o2 = __shfl_xor_sync(0xffffffffu, c2v, 1);
                float o3 = __shfl_xor_sync(0xffffffffu, c3v, 1);
                float zi = evenp ? c0 : o2;
                float zj = evenp ? c1 : o3;
                float zf = evenp ? o0 : c2v;
                float zo = evenp ? o1 : c3v;
                const int h = nwarp * 16 + nt * 2 + hpar;
                zi += bias_s[h];
                zj += bias_s[64 + h];
                zf += bias_s[128 + h];
                zo += bias_s[192 + h];
                const int ci = mt * 8 + nt;
                float cn = creg[ci] * sigf_(zf) + sigf_(zi) * tanhf_(zj);
                float h2 = tanhf_(cn) * sigf_(zo);
                creg[ci] = cn;
                // h_prev for next step
                __nv_bfloat16 hi = __float2bfloat16(h2);
                __nv_bfloat16 lo = __float2bfloat16(h2 - __bfloat162float(hi));
                *(unsigned short*)(sm + OFF_AH + b * (LDW * 2) + (64 + h) * 2) =
                    __bfloat16_as_ushort(hi);
                *(unsigned short*)(sm + OFF_AL + b * (LDW * 2) + (64 + h) * 2) =
                    __bfloat16_as_ushort(lo);
                if (l < NL - 1) {
                    gH[b * 64 + h] = (uint32_t)__bfloat16_as_ushort(hi) |
                                     ((uint32_t)__bfloat16_as_ushort(lo) << 16);
                } else {
                    part += h2 * Wd_s[t * 64 + h];
                }
            }
            if (l == NL - 1) ps[b * 8 + nwarp * 2 + hpar] = part;
        }

        if (l < NL - 1) {
            __threadfence();
            __syncthreads();
            if (tid == 0) {
                unsigned int one = 1u;
                asm volatile("st.release.gpu.global.b32 [%0], %1;"
                             :: "l"(&g_flags[(l * 2 + half) * NT + t]), "r"(one));
            }
        } else {
            __syncthreads();
            if (tid < MB) {
                const float* p = ps + tid * 8;
                float s = p[0] + p[1] + p[2] + p[3] + p[4] + p[5] + p[6] + p[7] +
                          bd[t];
                g_pred[(size_t)(half * MB + tid) * NT + t] = fmaxf(s, 0.0f);
            }
        }
    }
}

__global__ void finalize_kernel(const float* __restrict__ labels,
                                float* __restrict__ out, int out_size) {
    __shared__ float red[256];
    float s = 0.0f;
    for (int i = threadIdx.x; i < 128 * NT; i += 256) {
        float d = labels[i] - g_pred[i];
        s += d * d;
    }
    red[threadIdx.x] = s;
    __syncthreads();
    for (int st = 128; st > 0; st >>= 1) {
        if (threadIdx.x < st) red[threadIdx.x] += red[threadIdx.x + st];
        __syncthreads();
    }
    float loss = red[0] / (float)(128 * NT);

    if (out_size > 128 * NT) {
        for (int i = threadIdx.x; i < 128 * NT; i += 256) out[i] = g_pred[i];
        if (threadIdx.x == 0)
            for (int i = 128 * NT; i < out_size; ++i) out[i] = loss;
    } else if (out_size == 128 * NT) {
        for (int i = threadIdx.x; i < 128 * NT; i += 256) out[i] = g_pred[i];
    } else {
        for (int i = threadIdx.x; i < out_size; i += 256) out[i] = loss;
    }
}

extern "C" void kernel_launch(void* const* d_in, const int* in_sizes, int n_in,
                              void* d_out, int out_size) {
    const float* x      = (const float*)d_in[0];
    const float* labels = (const float*)d_in[1];
    const float* W0     = (const float*)d_in[2];
    const float* b0     = (const float*)d_in[3];
    const float* Wl     = (const float*)d_in[4];
    const float* bl     = (const float*)d_in[5];
    const float* Wd     = (const float*)d_in[6];
    const float* bd     = (const float*)d_in[7];
    float* out = (float*)d_out;

    cudaFuncSetAttribute(lstm_mma_kernel,
                         cudaFuncAttributeMaxDynamicSharedMemorySize, SMEM_BYTES);

    prep_weights<<<(NL * 32768 + 255) / 256, 256>>>(W0, Wl);
    reset_flags_kernel<<<32, 256>>>();
    dim3 grid(2, NL);
    lstm_mma_kernel<<<grid, THREADS, SMEM_BYTES>>>(x, b0, bl, Wd, bd);
    finalize_kernel<<<1, 256>>>(labels, out, out_size);
}

// round 5
// speedup vs baseline: 2.5993x; 1.2775x over previous
#include <cuda_runtime.h>
#include <cuda_bf16.h>
#include <cstdint>

// ---------------------------------------------------------------------------
// 64-layer x 64-timestep stacked LSTM, B=128, H=64.
// 128 persistent CTAs = (layer, batch-half), 256 threads.
// z[64,256] = A[64,128] @ W via mma.sync m16n8k16 bf16, exact 3-term split.
// Weight cols pair-interleaved: block0 n'=h*2+{i,j}, block1 128+h*2+{f,o}
//   -> each lane owns all 4 gates of its cells, zero shfls in epilogue.
// Split-K: h_prev half (k64..127) MMA issued BEFORE the inter-CTA flag wait.
// ---------------------------------------------------------------------------

#define NT 64
#define NL 64
#define MB 64
#define THREADS 256
#define LDW 136
#define A16 (16 * LDW * 2)

// weights, pair-interleaved + bf16 split: [split][layer][n'*128 + k]
__device__ __nv_bfloat16 g_Wsplit[2][NL][256 * 128];
// h handoff: [l][half][t][b*64+h], packed (hi | lo<<16)
__device__ uint32_t g_Hbuf[63 * 2 * NT * MB * 64];
__device__ unsigned int g_flags[63 * 2 * NT];
__device__ float g_pred[128 * NT];

// ---- SMEM byte offsets ----
#define OFF_WH 0
#define OFF_WL 69632
#define OFF_AH 139264
#define OFF_AL 156672
#define OFF_BIAS 174080
#define OFF_W0X 175104
#define OFF_XS 176128
#define OFF_WD 176384
#define OFF_PS 192768
#define SMEM_BYTES 197248

__device__ __forceinline__ uint32_t smem_u32(const void* p) {
    uint32_t a;
    asm("{ .reg .u64 t; cvta.to.shared.u64 t, %1; cvt.u32.u64 %0, t; }"
        : "=r"(a) : "l"(p));
    return a;
}
__device__ __forceinline__ void ldsm4(uint32_t r[4], uint32_t addr) {
    asm volatile("ldmatrix.sync.aligned.m8n8.x4.shared.b16 {%0,%1,%2,%3}, [%4];"
                 : "=r"(r[0]), "=r"(r[1]), "=r"(r[2]), "=r"(r[3]) : "r"(addr));
}
__device__ __forceinline__ void mma_bf16(float d[4], const uint32_t a[4],
                                         uint32_t b0, uint32_t b1) {
    asm volatile(
        "mma.sync.aligned.m16n8k16.row.col.f32.bf16.bf16.f32 "
        "{%0,%1,%2,%3}, {%4,%5,%6,%7}, {%8,%9}, {%0,%1,%2,%3};"
        : "+f"(d[0]), "+f"(d[1]), "+f"(d[2]), "+f"(d[3])
        : "r"(a[0]), "r"(a[1]), "r"(a[2]), "r"(a[3]), "r"(b0), "r"(b1));
}
__device__ __forceinline__ float sigf_(float z) {
    float e = __expf(-z);
    return __fdividef(1.0f, 1.0f + e);
}
__device__ __forceinline__ float tanhf_(float z) {
    z = fminf(fmaxf(z, -15.0f), 15.0f);
    float e = __expf(2.0f * z);
    return __fdividef(e - 1.0f, e + 1.0f);
}

// ---- weight prep: pair-interleave + exact bf16 2-split ----
__global__ void prep_weights(const float* __restrict__ W0,
                             const float* __restrict__ Wl) {
    int i = blockIdx.x * blockDim.x + threadIdx.x;
    if (i >= NL * 32768) return;
    int l = i >> 15, nk = i & 32767;
    int np = nk >> 7, k = nk & 127;
    int h, g;
    if (np < 128) { h = np >> 1; g = np & 1; }              // i=0, j=1
    else { int m = np - 128; h = m >> 1; g = 2 + (m & 1); } // f=2, o=3
    int n = g * 64 + h;
    float w;
    if (l == 0) {
        if (k < 64) w = 0.0f;                              // x handled in epilogue
        else w = W0[(size_t)(k - 63) * 256 + n];           // h_prev rows 1..64
    } else {
        w = Wl[((size_t)(l - 1) * 128 + k) * 256 + n];
    }
    __nv_bfloat16 hi = __float2bfloat16(w);
    __nv_bfloat16 lo = __float2bfloat16(w - __bfloat162float(hi));
    g_Wsplit[0][l][nk] = hi;
    g_Wsplit[1][l][nk] = lo;
}

__global__ void reset_flags_kernel() {
    unsigned int i = blockIdx.x * blockDim.x + threadIdx.x;
    if (i < 63u * 2u * NT) g_flags[i] = 0u;
}

#define DO_CHUNK(kk)                                                          \
    do {                                                                      \
        uint32_t ah0[4], ah1[4], al0[4], al1[4];                              \
        uint32_t bh[4][4], blo[4][4];                                         \
        ldsm4(ah0, sAH + (kk) * 32);                                          \
        ldsm4(ah1, sAH + A16 + (kk) * 32);                                    \
        ldsm4(al0, sAL + (kk) * 32);                                          \
        ldsm4(al1, sAL + A16 + (kk) * 32);                                    \
        ldsm4(bh[0], sWHij + (kk) * 32);                                      \
        ldsm4(bh[1], sWHij + A16 + (kk) * 32);                                \
        ldsm4(bh[2], sWHfo + (kk) * 32);                                      \
        ldsm4(bh[3], sWHfo + A16 + (kk) * 32);                                \
        ldsm4(blo[0], sWLij + (kk) * 32);                                     \
        ldsm4(blo[1], sWLij + A16 + (kk) * 32);                               \
        ldsm4(blo[2], sWLfo + (kk) * 32);                                     \
        ldsm4(blo[3], sWLfo + A16 + (kk) * 32);                               \
        _Pragma("unroll") for (int q = 0; q < 8; q++) {                       \
            int np = (q < 4) ? (q >> 1) : (2 + ((q - 4) >> 1));               \
            int hf = (q & 1) * 2;                                             \
            uint32_t b0 = bh[np][hf], b1 = bh[np][hf + 1];                    \
            uint32_t l0 = blo[np][hf], l1 = blo[np][hf + 1];                  \
            mma_bf16(acc[0][q], ah0, b0, b1);                                 \
            mma_bf16(acc[0][q], ah0, l0, l1);                                 \
            mma_bf16(acc[0][q], al0, b0, b1);                                 \
            mma_bf16(acc[1][q], ah1, b0, b1);                                 \
            mma_bf16(acc[1][q], ah1, l0, l1);                                 \
            mma_bf16(acc[1][q], al1, b0, b1);                                 \
        }                                                                     \
    } while (0)

__global__ void __launch_bounds__(THREADS, 1) lstm_mma_kernel(
    const float* __restrict__ x, const float* __restrict__ W0,
    const float* __restrict__ b0, const float* __restrict__ bl,
    const float* __restrict__ Wd, const float* __restrict__ bd) {
    extern __shared__ char sm[];
    const int tid = threadIdx.x, lane = tid & 31, warp = tid >> 5;
    const int half = blockIdx.x, l = blockIdx.y;
    const int mwarp = warp >> 2, nwarp = warp & 3;
    const uint32_t smb = smem_u32(sm);

    float* bias_s = (float*)(sm + OFF_BIAS);
    float* w0x_s  = (float*)(sm + OFF_W0X);
    float* x_s    = (float*)(sm + OFF_XS);
    float* Wd_s   = (float*)(sm + OFF_WD);
    float* ps     = (float*)(sm + OFF_PS);

    // ---- init ----
    for (int s = 0; s < 2; s++) {
        const uint32_t* src = (const uint32_t*)g_Wsplit[s][l];
        char* dst = sm + (s ? OFF_WL : OFF_WH);
        for (int i = tid; i < 16384; i += THREADS) {
            int n = i >> 6, kk = i & 63;
            *(uint32_t*)(dst + n * (LDW * 2) + kk * 4) = src[i];
        }
    }
    for (int i = tid; i < 256; i += THREADS)
        bias_s[i] = (l == 0) ? b0[i] : bl[(size_t)(l - 1) * 256 + i];
    if (l == 0)
        for (int i = tid; i < 256; i += THREADS) w0x_s[i] = W0[i];
    for (int i = tid; i < (2 * MB * LDW * 2) / 4; i += THREADS)
        ((uint32_t*)(sm + OFF_AH))[i] = 0u;
    if (l == NL - 1)
        for (int i = tid; i < 64 * 64; i += THREADS) Wd_s[i] = Wd[i];
    __syncthreads();

    // ---- lane ldmatrix bases ----
    const uint32_t aRow = ((uint32_t)((lane & 15) * LDW + (lane >> 4) * 8)) * 2u;
    const uint32_t sAH = smb + OFF_AH + aRow;
    const uint32_t sAL = smb + OFF_AL + aRow;
    const uint32_t bLane =
        ((uint32_t)((((lane >> 4) & 1) * 8 + (lane & 7)) * LDW +
                    ((lane >> 3) & 1) * 8)) * 2u;
    const uint32_t sWHij = smb + OFF_WH + (uint32_t)(nwarp * 32 * LDW) * 2u + bLane;
    const uint32_t sWHfo =
        smb + OFF_WH + (uint32_t)((128 + nwarp * 32) * LDW) * 2u + bLane;
    const uint32_t sWLij = sWHij + (OFF_WL - OFF_WH);
    const uint32_t sWLfo = sWHfo + (OFF_WL - OFF_WH);

    float creg[16];
#pragma unroll
    for (int i = 0; i < 16; i++) creg[i] = 0.0f;

    for (int t = 0; t < NT; ++t) {
        float acc[2][8][4];
#pragma unroll
        for (int i = 0; i < 2; i++)
#pragma unroll
            for (int j = 0; j < 8; j++)
#pragma unroll
                for (int c = 0; c < 4; c++) acc[i][j][c] = 0.0f;

        // ---- [A] h_prev half (k 64..127) — before any wait ----
        DO_CHUNK(4); DO_CHUNK(5); DO_CHUNK(6); DO_CHUNK(7);

        if (l > 0) {
            // ---- [B] acquire h_in ----
            if (tid == 0) {
                const unsigned int* fp = &g_flags[((l - 1) * 2 + half) * NT + t];
                unsigned int v;
                do {
                    asm volatile("ld.acquire.gpu.global.b32 %0, [%1];"
                                 : "=r"(v) : "l"(fp));
                } while (v == 0u);
            }
            __syncthreads();
            // ---- [C] stage h_in (cols 0..63) ----
            const uint32_t* src =
                g_Hbuf + (size_t)(((l - 1) * 2 + half) * NT + t) * 4096;
            int b = tid >> 2, h0 = (tid & 3) * 16;
            uint32_t u[16];
            const uint4* s4 = (const uint4*)(src + b * 64 + h0);
#pragma unroll
            for (int j = 0; j < 4; j++) {
                uint4 v = s4[j];
                u[j * 4] = v.x; u[j * 4 + 1] = v.y;
                u[j * 4 + 2] = v.z; u[j * 4 + 3] = v.w;
            }
#pragma unroll
            for (int j = 0; j < 16; j += 4) {
                uint2 hip, lop;
                hip.x = __byte_perm(u[j], u[j + 1], 0x5410);
                hip.y = __byte_perm(u[j + 2], u[j + 3], 0x5410);
                lop.x = __byte_perm(u[j], u[j + 1], 0x7632);
                lop.y = __byte_perm(u[j + 2], u[j + 3], 0x7632);
                *(uint2*)(sm + OFF_AH + b * (LDW * 2) + (h0 + j) * 2) = hip;
                *(uint2*)(sm + OFF_AL + b * (LDW * 2) + (h0 + j) * 2) = lop;
            }
            __syncthreads();
            // ---- [E] h_in half (k 0..63) ----
            DO_CHUNK(0); DO_CHUNK(1); DO_CHUNK(2); DO_CHUNK(3);
        } else {
            if (tid < MB) x_s[tid] = x[(size_t)(half * MB + tid) * NT + t];
        }
        __syncthreads();  // [F] ldsm done / x_s visible before epilogue writes

        // ---- [G] epilogue: all 4 gates local, zero shfl ----
        uint32_t* gH = (l < NL - 1)
            ? g_Hbuf + (size_t)((l * 2 + half) * NT + t) * 4096 : (uint32_t*)0;
#pragma unroll
        for (int mt = 0; mt < 2; mt++) {
#pragma unroll
            for (int rh = 0; rh < 2; rh++) {
                const int b = mwarp * 32 + mt * 16 + (lane >> 2) + rh * 8;
                float part = 0.0f;
                float xv = (l == 0) ? x_s[b] : 0.0f;
#pragma unroll
                for (int j = 0; j < 4; j++) {
                    const int h = nwarp * 16 + j * 4 + (lane & 3);
                    float zi = acc[mt][j][rh * 2]     + bias_s[h];
                    float zj = acc[mt][j][rh * 2 + 1] + bias_s[64 + h];
                    float zf = acc[mt][4 + j][rh * 2]     + bias_s[128 + h];
                    float zo = acc[mt][4 + j][rh * 2 + 1] + bias_s[192 + h];
                    if (l == 0) {
                        zi += xv * w0x_s[h];
                        zj += xv * w0x_s[64 + h];
                        zf += xv * w0x_s[128 + h];
                        zo += xv * w0x_s[192 + h];
                    }
                    const int ci = mt * 8 + rh * 4 + j;
                    float cn = creg[ci] * sigf_(zf) + sigf_(zi) * tanhf_(zj);
                    float h2 = tanhf_(cn) * sigf_(zo);
                    creg[ci] = cn;
                    __nv_bfloat16 hi = __float2bfloat16(h2);
                    __nv_bfloat16 lo =
                        __float2bfloat16(h2 - __bfloat162float(hi));
                    *(unsigned short*)(sm + OFF_AH + b * (LDW * 2) +
                                       (64 + h) * 2) = __bfloat16_as_ushort(hi);
                    *(unsigned short*)(sm + OFF_AL + b * (LDW * 2) +
                                       (64 + h) * 2) = __bfloat16_as_ushort(lo);
                    if (l < NL - 1) {
                        gH[b * 64 + h] = (uint32_t)__bfloat16_as_ushort(hi) |
                                         ((uint32_t)__bfloat16_as_ushort(lo) << 16);
                    } else {
                        part += h2 * Wd_s[t * 64 + h];
                    }
                }
                if (l == NL - 1)
                    ps[b * 17 + nwarp * 4 + (lane & 3)] = part;
            }
        }

        // ---- [H] publish ----
        if (l < NL - 1) {
            __syncthreads();  // all STG visible-before-release via bar + release
            if (tid == 0) {
                unsigned int one = 1u;
                asm volatile("st.release.gpu.global.b32 [%0], %1;"
                             :: "l"(&g_flags[(l * 2 + half) * NT + t]), "r"(one));
            }
        } else {
            __syncthreads();
            if (tid < MB) {
                const float* p = ps + tid * 17;
                float s = bd[t];
#pragma unroll
                for (int i = 0; i < 16; i++) s += p[i];
                g_pred[(size_t)(half * MB + tid) * NT + t] = fmaxf(s, 0.0f);
            }
        }
    }
}

__global__ void finalize_kernel(const float* __restrict__ labels,
                                float* __restrict__ out, int out_size) {
    __shared__ float red[256];
    float s = 0.0f;
    for (int i = threadIdx.x; i < 128 * NT; i += 256) {
        float d = labels[i] - g_pred[i];
        s += d * d;
    }
    red[threadIdx.x] = s;
    __syncthreads();
    for (int st = 128; st > 0; st >>= 1) {
        if (threadIdx.x < st) red[threadIdx.x] += red[threadIdx.x + st];
        __syncthreads();
    }
    float loss = red[0] / (float)(128 * NT);

    if (out_size > 128 * NT) {
        for (int i = threadIdx.x; i < 128 * NT; i += 256) out[i] = g_pred[i];
        if (threadIdx.x == 0)
            for (int i = 128 * NT; i < out_size; ++i) out[i] = loss;
    } else if (out_size == 128 * NT) {
        for (int i = threadIdx.x; i < 128 * NT; i += 256) out[i] = g_pred[i];
    } else {
        for (int i = threadIdx.x; i < out_size; i += 256) out[i] = loss;
    }
}

extern "C" void kernel_launch(void* const* d_in, const int* in_sizes, int n_in,
                              void* d_out, int out_size) {
    const float* x      = (const float*)d_in[0];
    const float* labels = (const float*)d_in[1];
    const float* W0     = (const float*)d_in[2];
    const float* b0     = (const float*)d_in[3];
    const float* Wl     = (const float*)d_in[4];
    const float* bl     = (const float*)d_in[5];
    const float* Wd     = (const float*)d_in[6];
    const float* bd     = (const float*)d_in[7];
    float* out = (float*)d_out;

    cudaFuncSetAttribute(lstm_mma_kernel,
                         cudaFuncAttributeMaxDynamicSharedMemorySize, SMEM_BYTES);

    prep_weights<<<(NL * 32768 + 255) / 256, 256>>>(W0, Wl);
    reset_flags_kernel<<<32, 256>>>();
    dim3 grid(2, NL);
    lstm_mma_kernel<<<grid, THREADS, SMEM_BYTES>>>(x, W0, b0, bl, Wd, bd);
    finalize_kernel<<<1, 256>>>(labels, out, out_size);
}

// round 6
// speedup vs baseline: 2.9354x; 1.1293x over previous
#include <cuda_runtime.h>
#include <cuda_bf16.h>
#include <cstdint>

// ---------------------------------------------------------------------------
// 64-layer x 64-timestep stacked LSTM, B=128, H=64.
// 128 persistent CTAs = (layer, batch-half), 256 threads.
// z[64,256] = A[64,128] @ W via mma.sync m16n8k16 bf16, exact 3-term split.
// Weight cols pair-interleaved; zero-shfl epilogue; split-K before flag wait.
// This round: MUFU.TANH activations, in-kernel weight prep, fused finalize.
// ---------------------------------------------------------------------------

#define NT 64
#define NL 64
#define MB 64
#define THREADS 256
#define LDW 136
#define A16 (16 * LDW * 2)

// h handoff: [l][half][t][b*64+h], packed (hi | lo<<16)
__device__ uint32_t g_Hbuf[63 * 2 * NT * MB * 64];
__device__ unsigned int g_flags[63 * 2 * NT];
__device__ float g_pred[128 * NT];
__device__ unsigned int g_done;

// ---- SMEM byte offsets ----
#define OFF_WH 0
#define OFF_WL 69632
#define OFF_AH 139264
#define OFF_AL 156672
#define OFF_BIAS 174080
#define OFF_W0X 175104
#define OFF_XS 176128
#define OFF_WD 176384
#define OFF_PS 192768
#define SMEM_BYTES 197248

__device__ __forceinline__ uint32_t smem_u32(const void* p) {
    uint32_t a;
    asm("{ .reg .u64 t; cvta.to.shared.u64 t, %1; cvt.u32.u64 %0, t; }"
        : "=r"(a) : "l"(p));
    return a;
}
__device__ __forceinline__ void ldsm4(uint32_t r[4], uint32_t addr) {
    asm volatile("ldmatrix.sync.aligned.m8n8.x4.shared.b16 {%0,%1,%2,%3}, [%4];"
                 : "=r"(r[0]), "=r"(r[1]), "=r"(r[2]), "=r"(r[3]) : "r"(addr));
}
__device__ __forceinline__ void mma_bf16(float d[4], const uint32_t a[4],
                                         uint32_t b0, uint32_t b1) {
    asm volatile(
        "mma.sync.aligned.m16n8k16.row.col.f32.bf16.bf16.f32 "
        "{%0,%1,%2,%3}, {%4,%5,%6,%7}, {%8,%9}, {%0,%1,%2,%3};"
        : "+f"(d[0]), "+f"(d[1]), "+f"(d[2]), "+f"(d[3])
        : "r"(a[0]), "r"(a[1]), "r"(a[2]), "r"(a[3]), "r"(b0), "r"(b1));
}
__device__ __forceinline__ float tanh_fast(float x) {
    float y;
    asm("tanh.approx.f32 %0, %1;" : "=f"(y) : "f"(x));
    return y;
}
__device__ __forceinline__ float sig_fast(float x) {
    return fmaf(0.5f, tanh_fast(0.5f * x), 0.5f);
}

__global__ void reset_kernel() {
    unsigned int i = blockIdx.x * blockDim.x + threadIdx.x;
    if (i < 63u * 2u * NT) g_flags[i] = 0u;
    if (i == 0) g_done = 0u;
}

#define DO_CHUNK(kk)                                                          \
    do {                                                                      \
        uint32_t ah0[4], ah1[4], al0[4], al1[4];                              \
        uint32_t bh[4][4], blo[4][4];                                         \
        ldsm4(ah0, sAH + (kk) * 32);                                          \
        ldsm4(ah1, sAH + A16 + (kk) * 32);                                    \
        ldsm4(al0, sAL + (kk) * 32);                                          \
        ldsm4(al1, sAL + A16 + (kk) * 32);                                    \
        ldsm4(bh[0], sWHij + (kk) * 32);                                      \
        ldsm4(bh[1], sWHij + A16 + (kk) * 32);                                \
        ldsm4(bh[2], sWHfo + (kk) * 32);                                      \
        ldsm4(bh[3], sWHfo + A16 + (kk) * 32);                                \
        ldsm4(blo[0], sWLij + (kk) * 32);                                     \
        ldsm4(blo[1], sWLij + A16 + (kk) * 32);                               \
        ldsm4(blo[2], sWLfo + (kk) * 32);                                     \
        ldsm4(blo[3], sWLfo + A16 + (kk) * 32);                               \
        _Pragma("unroll") for (int q = 0; q < 8; q++) {                       \
            int np = (q < 4) ? (q >> 1) : (2 + ((q - 4) >> 1));               \
            int hf = (q & 1) * 2;                                             \
            uint32_t b0 = bh[np][hf], b1 = bh[np][hf + 1];                    \
            uint32_t l0 = blo[np][hf], l1 = blo[np][hf + 1];                  \
            mma_bf16(acc[0][q], ah0, b0, b1);                                 \
            mma_bf16(acc[0][q], ah0, l0, l1);                                 \
            mma_bf16(acc[0][q], al0, b0, b1);                                 \
            mma_bf16(acc[1][q], ah1, b0, b1);                                 \
            mma_bf16(acc[1][q], ah1, l0, l1);                                 \
            mma_bf16(acc[1][q], al1, b0, b1);                                 \
        }                                                                     \
    } while (0)

__global__ void __launch_bounds__(THREADS, 1) lstm_mma_kernel(
    const float* __restrict__ x, const float* __restrict__ W0,
    const float* __restrict__ b0, const float* __restrict__ bl,
    const float* __restrict__ Wd, const float* __restrict__ bd,
    const float* __restrict__ Wl, const float* __restrict__ labels,
    float* __restrict__ out, int out_size) {
    extern __shared__ char sm[];
    const int tid = threadIdx.x, lane = tid & 31, warp = tid >> 5;
    const int half = blockIdx.x, l = blockIdx.y;
    const int mwarp = warp >> 2, nwarp = warp & 3;
    const uint32_t smb = smem_u32(sm);

    float* bias_s = (float*)(sm + OFF_BIAS);
    float* w0x_s  = (float*)(sm + OFF_W0X);
    float* x_s    = (float*)(sm + OFF_XS);
    float* Wd_s   = (float*)(sm + OFF_WD);
    float* ps     = (float*)(sm + OFF_PS);

    // ---- init: in-place weight prep (coalesced fp32 read -> split SMEM) ----
    for (int i = tid; i < 32768; i += THREADS) {
        int k = i >> 8, n = i & 255;  // consecutive tid -> consecutive n
        float w;
        if (l == 0) {
            w = (k < 64) ? 0.0f : W0[(size_t)(k - 63) * 256 + n];
        } else {
            w = Wl[((size_t)(l - 1) * 128 + k) * 256 + n];
        }
        int g = n >> 6, h = n & 63;
        int np = (g < 2) ? (h * 2 + g) : (128 + h * 2 + (g - 2));
        __nv_bfloat16 hi = __float2bfloat16(w);
        __nv_bfloat16 lo = __float2bfloat16(w - __bfloat162float(hi));
        *(unsigned short*)(sm + OFF_WH + np * (LDW * 2) + k * 2) =
            __bfloat16_as_ushort(hi);
        *(unsigned short*)(sm + OFF_WL + np * (LDW * 2) + k * 2) =
            __bfloat16_as_ushort(lo);
    }
    for (int i = tid; i < 256; i += THREADS)
        bias_s[i] = (l == 0) ? b0[i] : bl[(size_t)(l - 1) * 256 + i];
    if (l == 0)
        for (int i = tid; i < 256; i += THREADS) w0x_s[i] = W0[i];
    for (int i = tid; i < (2 * MB * LDW * 2) / 4; i += THREADS)
        ((uint32_t*)(sm + OFF_AH))[i] = 0u;
    if (l == NL - 1)
        for (int i = tid; i < 64 * 64; i += THREADS) Wd_s[i] = Wd[i];
    __syncthreads();

    // ---- lane ldmatrix bases ----
    const uint32_t aRow = ((uint32_t)((lane & 15) * LDW + (lane >> 4) * 8)) * 2u;
    const uint32_t sAH = smb + OFF_AH + aRow;
    const uint32_t sAL = smb + OFF_AL + aRow;
    const uint32_t bLane =
        ((uint32_t)((((lane >> 4) & 1) * 8 + (lane & 7)) * LDW +
                    ((lane >> 3) & 1) * 8)) * 2u;
    const uint32_t sWHij = smb + OFF_WH + (uint32_t)(nwarp * 32 * LDW) * 2u + bLane;
    const uint32_t sWHfo =
        smb + OFF_WH + (uint32_t)((128 + nwarp * 32) * LDW) * 2u + bLane;
    const uint32_t sWLij = sWHij + (OFF_WL - OFF_WH);
    const uint32_t sWLfo = sWHfo + (OFF_WL - OFF_WH);

    float creg[16];
#pragma unroll
    for (int i = 0; i < 16; i++) creg[i] = 0.0f;

    for (int t = 0; t < NT; ++t) {
        float acc[2][8][4];
#pragma unroll
        for (int i = 0; i < 2; i++)
#pragma unroll
            for (int j = 0; j < 8; j++)
#pragma unroll
                for (int c = 0; c < 4; c++) acc[i][j][c] = 0.0f;

        // ---- [A] h_prev half (k 64..127) — before any wait ----
        DO_CHUNK(4); DO_CHUNK(5); DO_CHUNK(6); DO_CHUNK(7);

        if (l > 0) {
            // ---- [B] acquire h_in ----
            if (tid == 0) {
                const unsigned int* fp = &g_flags[((l - 1) * 2 + half) * NT + t];
                unsigned int v;
                do {
                    asm volatile("ld.acquire.gpu.global.b32 %0, [%1];"
                                 : "=r"(v) : "l"(fp));
                } while (v == 0u);
            }
            __syncthreads();
            // ---- [C] stage h_in (cols 0..63) ----
            const uint32_t* src =
                g_Hbuf + (size_t)(((l - 1) * 2 + half) * NT + t) * 4096;
            int b = tid >> 2, h0 = (tid & 3) * 16;
            uint32_t u[16];
            const uint4* s4 = (const uint4*)(src + b * 64 + h0);
#pragma unroll
            for (int j = 0; j < 4; j++) {
                uint4 v = s4[j];
                u[j * 4] = v.x; u[j * 4 + 1] = v.y;
                u[j * 4 + 2] = v.z; u[j * 4 + 3] = v.w;
            }
#pragma unroll
            for (int j = 0; j < 16; j += 4) {
                uint2 hip, lop;
                hip.x = __byte_perm(u[j], u[j + 1], 0x5410);
                hip.y = __byte_perm(u[j + 2], u[j + 3], 0x5410);
                lop.x = __byte_perm(u[j], u[j + 1], 0x7632);
                lop.y = __byte_perm(u[j + 2], u[j + 3], 0x7632);
                *(uint2*)(sm + OFF_AH + b * (LDW * 2) + (h0 + j) * 2) = hip;
                *(uint2*)(sm + OFF_AL + b * (LDW * 2) + (h0 + j) * 2) = lop;
            }
            __syncthreads();
            // ---- [E] h_in half (k 0..63) ----
            DO_CHUNK(0); DO_CHUNK(1); DO_CHUNK(2); DO_CHUNK(3);
        } else {
            if (tid < MB) x_s[tid] = x[(size_t)(half * MB + tid) * NT + t];
        }
        __syncthreads();  // [F]

        // ---- [G] epilogue: all 4 gates local, MUFU.TANH activations ----
        uint32_t* gH = (l < NL - 1)
            ? g_Hbuf + (size_t)((l * 2 + half) * NT + t) * 4096 : (uint32_t*)0;
#pragma unroll
        for (int mt = 0; mt < 2; mt++) {
#pragma unroll
            for (int rh = 0; rh < 2; rh++) {
                const int b = mwarp * 32 + mt * 16 + (lane >> 2) + rh * 8;
                float part = 0.0f;
                float xv = (l == 0) ? x_s[b] : 0.0f;
#pragma unroll
                for (int j = 0; j < 4; j++) {
                    const int h = nwarp * 16 + j * 4 + (lane & 3);
                    float zi = acc[mt][j][rh * 2]     + bias_s[h];
                    float zj = acc[mt][j][rh * 2 + 1] + bias_s[64 + h];
                    float zf = acc[mt][4 + j][rh * 2]     + bias_s[128 + h];
                    float zo = acc[mt][4 + j][rh * 2 + 1] + bias_s[192 + h];
                    if (l == 0) {
                        zi += xv * w0x_s[h];
                        zj += xv * w0x_s[64 + h];
                        zf += xv * w0x_s[128 + h];
                        zo += xv * w0x_s[192 + h];
                    }
                    const int ci = mt * 8 + rh * 4 + j;
                    float cn = fmaf(creg[ci], sig_fast(zf),
                                    sig_fast(zi) * tanh_fast(zj));
                    float h2 = tanh_fast(cn) * sig_fast(zo);
                    creg[ci] = cn;
                    __nv_bfloat16 hi = __float2bfloat16(h2);
                    __nv_bfloat16 lo =
                        __float2bfloat16(h2 - __bfloat162float(hi));
                    *(unsigned short*)(sm + OFF_AH + b * (LDW * 2) +
                                       (64 + h) * 2) = __bfloat16_as_ushort(hi);
                    *(unsigned short*)(sm + OFF_AL + b * (LDW * 2) +
                                       (64 + h) * 2) = __bfloat16_as_ushort(lo);
                    if (l < NL - 1) {
                        gH[b * 64 + h] = (uint32_t)__bfloat16_as_ushort(hi) |
                                         ((uint32_t)__bfloat16_as_ushort(lo) << 16);
                    } else {
                        part += h2 * Wd_s[t * 64 + h];
                    }
                }
                if (l == NL - 1)
                    ps[b * 17 + nwarp * 4 + (lane & 3)] = part;
            }
        }

        // ---- [H] publish ----
        if (l < NL - 1) {
            __syncthreads();
            if (tid == 0) {
                unsigned int one = 1u;
                asm volatile("st.release.gpu.global.b32 [%0], %1;"
                             :: "l"(&g_flags[(l * 2 + half) * NT + t]), "r"(one));
            }
        } else {
            __syncthreads();
            if (tid < MB) {
                const float* p = ps + tid * 17;
                float s = bd[t];
#pragma unroll
                for (int i = 0; i < 16; i++) s += p[i];
                g_pred[(size_t)(half * MB + tid) * NT + t] = fmaxf(s, 0.0f);
            }
        }
    }

    // ---- fused finalize: top CTAs signal; CTA(63,0) reduces loss ----
    if (l == NL - 1) {
        __threadfence();
        __syncthreads();
        if (tid == 0) atomicAdd(&g_done, 1u);
        if (half == 0) {
            if (tid == 0) {
                unsigned int v;
                do {
                    asm volatile("ld.acquire.gpu.global.b32 %0, [%1];"
                                 : "=r"(v) : "l"(&g_done));
                } while (v < 2u);
            }
            __syncthreads();
            float s = 0.0f;
            for (int i = tid; i < 128 * NT; i += THREADS) {
                float d = labels[i] - __ldcg(&g_pred[i]);
                s += d * d;
            }
            float* red = (float*)(sm + OFF_PS);
            red[tid] = s;
            __syncthreads();
            for (int st = 128; st > 0; st >>= 1) {
                if (tid < st) red[tid] += red[tid + st];
                __syncthreads();
            }
            float loss = red[0] / (float)(128 * NT);
            if (out_size > 128 * NT) {
                for (int i = tid; i < 128 * NT; i += THREADS)
                    out[i] = __ldcg(&g_pred[i]);
                if (tid == 0)
                    for (int i = 128 * NT; i < out_size; ++i) out[i] = loss;
            } else if (out_size == 128 * NT) {
                for (int i = tid; i < 128 * NT; i += THREADS)
                    out[i] = __ldcg(&g_pred[i]);
            } else {
                for (int i = tid; i < out_size; i += THREADS) out[i] = loss;
            }
        }
    }
}

extern "C" void kernel_launch(void* const* d_in, const int* in_sizes, int n_in,
                              void* d_out, int out_size) {
    const float* x      = (const float*)d_in[0];
    const float* labels = (const float*)d_in[1];
    const float* W0     = (const float*)d_in[2];
    const float* b0     = (const float*)d_in[3];
    const float* Wl     = (const float*)d_in[4];
    const float* bl     = (const float*)d_in[5];
    const float* Wd     = (const float*)d_in[6];
    const float* bd     = (const float*)d_in[7];
    float* out = (float*)d_out;

    cudaFuncSetAttribute(lstm_mma_kernel,
                         cudaFuncAttributeMaxDynamicSharedMemorySize, SMEM_BYTES);

    reset_kernel<<<32, 256>>>();
    dim3 grid(2, NL);
    lstm_mma_kernel<<<grid, THREADS, SMEM_BYTES>>>(x, W0, b0, bl, Wd, bd, Wl,
                                                   labels, out, out_size);
}